// round 8
// baseline (speedup 1.0000x reference)
#include <cuda_runtime.h>

// x: (32, 1, 1024, 1024) fp32. out same shape.
#define IMG_N  32
#define HDIM   1024
#define WDIM   1024
#define RSTRIP 16                       // rows per block strip
#define STRIPS 64                       // strips per image
#define IMGS_PER_PHASE 4
#define PHASES (IMG_N / IMGS_PER_PHASE) // 8
#define GRID   (IMGS_PER_PHASE * STRIPS)// 256 blocks, all co-resident (2/SM)
#define RING   6                        // rows in flight (distance-3 pipeline)

// Per-phase per-block partial sums (each slot written before read, same launch).
__device__ double g_ps [PHASES][GRID];
__device__ double g_pss[PHASES][GRID];
__device__ unsigned g_bar;              // grid barrier counter

__global__ void reset_bar_kernel() { g_bar = 0u; }

// ---------------------------------------------------------------- loads/halo
template<bool INTERIOR>
__device__ __forceinline__ void load_row_t(const float* __restrict__ base, int row,
                                           int col, int lane,
                                           float4& v, float& el, float& er) {
    if (!INTERIOR) {
        if (row < 0 || row >= HDIM) {
            v = make_float4(0.f, 0.f, 0.f, 0.f); el = 0.f; er = 0.f; return;
        }
    }
    const float* p = base + (size_t)row * WDIM;
    v = *(const float4*)(p + col);
    el = 0.f; er = 0.f;
    if (lane == 0  && col > 0)        el = __ldg(p + col - 1);
    if (lane == 31 && col + 4 < WDIM) er = __ldg(p + col + 4);
}

__device__ __forceinline__ void make_halo(const float4& v, float el, float er,
                                          int lane, float& l, float& r) {
    float lu = __shfl_up_sync(0xffffffffu,  v.w, 1);
    float rd = __shfl_down_sync(0xffffffffu, v.x, 1);
    l = (lane == 0)  ? el : lu;
    r = (lane == 31) ? er : rd;
}

// z = center - (L + 2*DL + 4*D + 8*DR + 16*R + 32*UR + 64*U + 128*UL)/255
__device__ __forceinline__ void stencil4(const float4& u, float ul, float ur,
                                         const float4& c, float cl, float cr,
                                         const float4& d, float dl, float dr,
                                         float z[4]) {
    const float INV255 = 1.0f / 255.0f;
    z[0] = c.x - (cl  + 2.f*dl  + 4.f*d.x + 8.f*d.y + 16.f*c.y + 32.f*u.y + 64.f*u.x + 128.f*ul ) * INV255;
    z[1] = c.y - (c.x + 2.f*d.x + 4.f*d.y + 8.f*d.z + 16.f*c.z + 32.f*u.z + 64.f*u.y + 128.f*u.x) * INV255;
    z[2] = c.z - (c.y + 2.f*d.y + 4.f*d.z + 8.f*d.w + 16.f*c.w + 32.f*u.w + 64.f*u.z + 128.f*u.y) * INV255;
    z[3] = c.w - (c.z + 2.f*d.z + 4.f*d.w + 8.f*dr  + 16.f*cr  + 32.f*ur  + 64.f*u.w + 128.f*u.z) * INV255;
}

template<bool INTERIOR>
__device__ __forceinline__ void preload_ring(const float* __restrict__ base, int r0,
                                             int col, int lane,
                                             float4 v[RING], float el[RING], float er[RING]) {
    #pragma unroll
    for (int k = 0; k < RING - 1; k++)          // abs rows r0-1 .. r0+3
        load_row_t<INTERIOR>(base, r0 - 1 + k, col, lane, v[k], el[k], er[k]);
}

// Compute z for the 16-row strip into smem (thread-private columns), plus stats.
template<bool INTERIOR>
__device__ __forceinline__ void compute_strip(const float* __restrict__ base, int r0,
                                              int col, int lane,
                                              float4 v[RING], float el[RING], float er[RING],
                                              float* __restrict__ zbuf,
                                              float& s, float& ss) {
    float l[RING], r[RING];
    make_halo(v[0], el[0], er[0], lane, l[0], r[0]);
    make_halo(v[1], el[1], er[1], lane, l[1], r[1]);
    s = 0.f; ss = 0.f;
    #pragma unroll
    for (int i = 0; i < RSTRIP; i++) {
        if (i < RSTRIP - 3) {                    // load abs row r0+i+4
            const int rel = (i + RING - 1) % RING;
            load_row_t<INTERIOR>(base, r0 + i + 4, col, lane, v[rel], el[rel], er[rel]);
        }
        const int a = i % RING, b = (i + 1) % RING, c = (i + 2) % RING;
        make_halo(v[c], el[c], er[c], lane, l[c], r[c]);
        float z[4];
        stencil4(v[a], l[a], r[a], v[b], l[b], r[b], v[c], l[c], r[c], z);
        s  += (z[0] + z[1]) + (z[2] + z[3]);
        ss += (z[0]*z[0] + z[1]*z[1]) + (z[2]*z[2] + z[3]*z[3]);
        *(float4*)(zbuf + i * WDIM + col) = make_float4(z[0], z[1], z[2], z[3]);
    }
}

// Grid barrier: all GRID blocks are co-resident (see launch config), so a
// simple arrive-and-spin counter is deadlock-free. Counter is monotonic within
// a launch; reset_bar_kernel zeroes it before each (replayed) launch.
__device__ __forceinline__ void grid_sync(unsigned target) {
    __syncthreads();
    if (threadIdx.x == 0) {
        __threadfence();                         // release partials
        atomicAdd(&g_bar, 1u);
        while (*(volatile unsigned*)&g_bar < target) __nanosleep(64);
        __threadfence();                         // acquire others' partials
    }
    __syncthreads();
}

// ------------------------------------------------------------- fused kernel
__global__ void __launch_bounds__(256, 2) ltpe_fused(const float* __restrict__ x,
                                                     float* __restrict__ out) {
    extern __shared__ float smem[];
    float*  zbuf = smem;                          // 16*1024 floats = 64KB
    double* rs   = (double*)(smem + RSTRIP * WDIM);
    double* rss  = rs + 64;
    __shared__ float ws[8], wss[8];
    __shared__ float s_mean, s_inv;

    const int b      = blockIdx.x;
    const int strip  = b & (STRIPS - 1);
    const int imgblk = b >> 6;                    // 0..3
    const int r0     = strip * RSTRIP;
    const int col    = threadIdx.x * 4;
    const int lane   = threadIdx.x & 31;
    const int wid    = threadIdx.x >> 5;
    const bool interior = (strip != 0) && (strip != STRIPS - 1);

    float4 v[RING]; float el[RING], er[RING];

    // Prologue: preload ring for phase 0.
    {
        const float* base0 = x + (size_t)imgblk * HDIM * WDIM;
        if (interior) preload_ring<true >(base0, r0, col, lane, v, el, er);
        else          preload_ring<false>(base0, r0, col, lane, v, el, er);
    }

    for (int g = 0; g < PHASES; g++) {
        const int img = g * IMGS_PER_PHASE + imgblk;
        const float* ibase = x + (size_t)img * HDIM * WDIM;

        float s, ss;
        if (interior) compute_strip<true >(ibase, r0, col, lane, v, el, er, zbuf, s, ss);
        else          compute_strip<false>(ibase, r0, col, lane, v, el, er, zbuf, s, ss);

        // Block-reduce stats -> per-block partials (fixed order, deterministic).
        #pragma unroll
        for (int o = 16; o > 0; o >>= 1) {
            s  += __shfl_xor_sync(0xffffffffu, s,  o);
            ss += __shfl_xor_sync(0xffffffffu, ss, o);
        }
        if (lane == 0) { ws[wid] = s; wss[wid] = ss; }
        __syncthreads();
        if (threadIdx.x == 0) {
            float S = 0.f, SS = 0.f;
            #pragma unroll
            for (int i = 0; i < 8; i++) { S += ws[i]; SS += wss[i]; }
            g_ps [g][b] = (double)S;
            g_pss[g][b] = (double)SS;
        }

        // Preload NEXT phase's ring BEFORE the barrier: DRAM round-trips
        // overlap the barrier wait instead of idling.
        if (g + 1 < PHASES) {
            const float* nbase = ibase + (size_t)IMGS_PER_PHASE * HDIM * WDIM;
            if (interior) preload_ring<true >(nbase, r0, col, lane, v, el, er);
            else          preload_ring<false>(nbase, r0, col, lane, v, el, er);
        }

        grid_sync((unsigned)(g + 1) * GRID);

        // Reduce the 64 partials of MY image (parallel loads, fixed-order tree).
        if (threadIdx.x < 64) {
            rs [threadIdx.x] = g_ps [g][imgblk * 64 + threadIdx.x];
            rss[threadIdx.x] = g_pss[g][imgblk * 64 + threadIdx.x];
        }
        __syncthreads();
        #pragma unroll
        for (int o = 32; o > 0; o >>= 1) {
            if (threadIdx.x < o) {
                rs [threadIdx.x] += rs [threadIdx.x + o];
                rss[threadIdx.x] += rss[threadIdx.x + o];
            }
            __syncthreads();
        }
        if (threadIdx.x == 0) {
            const double N = (double)HDIM * WDIM;
            double mm  = rs[0] / N;
            double var = rss[0] / N - mm * mm;
            s_mean = (float)mm;
            // o = 0.5*z + 0.5 with IN eps=1e-5 => normalize z with eps' = 4e-5
            s_inv  = (float)rsqrt(var + 4e-5);
        }
        __syncthreads();
        const float m = s_mean, inv = s_inv;

        // Normalize my smem z (thread-private columns) and stream out.
        float* obase = out + (size_t)img * HDIM * WDIM;
        #pragma unroll
        for (int i = 0; i < RSTRIP; i++) {
            float4 z = *(float4*)(zbuf + i * WDIM + col);
            float4 o4;
            o4.x = (z.x - m) * inv;
            o4.y = (z.y - m) * inv;
            o4.z = (z.z - m) * inv;
            o4.w = (z.w - m) * inv;
            __stcs((float4*)(obase + (size_t)(r0 + i) * WDIM + col), o4);
        }
        // zbuf reuse next phase is safe: each thread reads/writes only its own
        // columns; s_mean/s_inv rewrites are ordered by grid_sync's syncthreads.
    }
}

// ------------------------------------------------------------------ launch
#define SMEM_BYTES (RSTRIP * WDIM * sizeof(float) + 2 * 64 * sizeof(double))

extern "C" void kernel_launch(void* const* d_in, const int* in_sizes, int n_in,
                              void* d_out, int out_size) {
    const float* x   = (const float*)d_in[0];
    float*       out = (float*)d_out;

    // Idempotent, not a stream op; required for >48KB dynamic smem.
    cudaFuncSetAttribute(ltpe_fused, cudaFuncAttributeMaxDynamicSharedMemorySize,
                         (int)SMEM_BYTES);

    reset_bar_kernel<<<1, 1>>>();
    ltpe_fused<<<GRID, 256, SMEM_BYTES>>>(x, out);
}